// round 3
// baseline (speedup 1.0000x reference)
#include <cuda_runtime.h>
#include <cstdint>
#include <cstdio>

#define DMODEL 2048
#define NHEADS 16
#define HDIM   128
#define BATCH  2
#define SEQ    2048
#define MROWS  (BATCH*SEQ)   // 4096

// ---------------- scratch (device globals: allocation-free) ----------------
__device__ float g_q[(size_t)MROWS * DMODEL];
__device__ float g_k[(size_t)MROWS * DMODEL];
__device__ float g_v[(size_t)MROWS * DMODEL];
__device__ float g_att[(size_t)MROWS * DMODEL];

// ---------------- helpers ----------------
__device__ __forceinline__ uint32_t f2tf(float x) {
    uint32_t r;
    asm("cvt.rna.tf32.f32 %0, %1;" : "=r"(r) : "f"(x));
    return r;
}

__device__ __forceinline__ void mma_tf32(float* c, const uint32_t* a, const uint32_t* b) {
    asm("mma.sync.aligned.m16n8k8.row.col.f32.tf32.tf32.f32 "
        "{%0,%1,%2,%3}, {%4,%5,%6,%7}, {%8,%9}, {%0,%1,%2,%3};"
        : "+f"(c[0]), "+f"(c[1]), "+f"(c[2]), "+f"(c[3])
        : "r"(a[0]), "r"(a[1]), "r"(a[2]), "r"(a[3]),
          "r"(b[0]), "r"(b[1]));
}

// ---------------- GEMM: C[M,N] = (A[M,K] @ W[N,K]^T + bias) * scale ----------------
// CTA tile 128x128, k-tile 32, 8 warps (2x4), warp tile 64x32, m16n8k8 tf32.
#define GT_K 32
#define GLD  36   // 32 + 4 pad (stride%32==4 -> conflict-free frag loads)

__global__ void __launch_bounds__(256, 1) gemm_bias_tf32(
    const float* __restrict__ A, const float* __restrict__ W,
    const float* __restrict__ bias, float* __restrict__ C,
    int M, int N, int K, float scale)
{
    __shared__ uint32_t As[128][GLD];
    __shared__ uint32_t Ws[128][GLD];

    const int tid  = threadIdx.x;
    const int ctaN = blockIdx.x * 128;
    const int ctaM = blockIdx.y * 128;

    const int warp = tid >> 5, lane = tid & 31;
    const int g = lane >> 2, tg = lane & 3;
    const int wm = (warp & 1) * 64;
    const int wn = (warp >> 1) * 32;

    const int lr = tid >> 3;        // 0..31
    const int lc = (tid & 7) * 4;   // 0..28

    const float* Abase = A + (size_t)(ctaM + lr) * K + lc;
    const float* Wbase = W + (size_t)(ctaN + lr) * K + lc;

    float acc[4][4][4];
#pragma unroll
    for (int mt = 0; mt < 4; mt++)
#pragma unroll
        for (int nt = 0; nt < 4; nt++)
#pragma unroll
            for (int j = 0; j < 4; j++) acc[mt][nt][j] = 0.f;

    const int nk = K / GT_K;

    // preload tile 0 into smem (converted to tf32)
#pragma unroll
    for (int p = 0; p < 4; p++) {
        float4 va = *(const float4*)(Abase + (size_t)(p * 32) * K);
        float4 vw = *(const float4*)(Wbase + (size_t)(p * 32) * K);
        uint4 ua = make_uint4(f2tf(va.x), f2tf(va.y), f2tf(va.z), f2tf(va.w));
        uint4 uw = make_uint4(f2tf(vw.x), f2tf(vw.y), f2tf(vw.z), f2tf(vw.w));
        *(uint4*)&As[lr + p * 32][lc] = ua;
        *(uint4*)&Ws[lr + p * 32][lc] = uw;
    }
    __syncthreads();

    for (int kt = 0; kt < nk; kt++) {
        float4 pa[4], pw[4];
        const bool pre = (kt + 1 < nk);
        if (pre) {
            const float* An = Abase + (size_t)(kt + 1) * GT_K;
            const float* Wn = Wbase + (size_t)(kt + 1) * GT_K;
#pragma unroll
            for (int p = 0; p < 4; p++) {
                pa[p] = *(const float4*)(An + (size_t)(p * 32) * K);
                pw[p] = *(const float4*)(Wn + (size_t)(p * 32) * K);
            }
        }

#pragma unroll
        for (int ks = 0; ks < 4; ks++) {
            uint32_t a[4][4];
#pragma unroll
            for (int mt = 0; mt < 4; mt++) {
                int r = wm + mt * 16 + g;
                int c = ks * 8 + tg;
                a[mt][0] = As[r][c];
                a[mt][1] = As[r + 8][c];
                a[mt][2] = As[r][c + 4];
                a[mt][3] = As[r + 8][c + 4];
            }
            uint32_t bfr[4][2];
#pragma unroll
            for (int nt = 0; nt < 4; nt++) {
                int rn = wn + nt * 8 + g;
                bfr[nt][0] = Ws[rn][ks * 8 + tg];
                bfr[nt][1] = Ws[rn][ks * 8 + tg + 4];
            }
#pragma unroll
            for (int mt = 0; mt < 4; mt++)
#pragma unroll
                for (int nt = 0; nt < 4; nt++)
                    mma_tf32(acc[mt][nt], a[mt], bfr[nt]);
        }
        __syncthreads();
        if (pre) {
#pragma unroll
            for (int p = 0; p < 4; p++) {
                uint4 ua = make_uint4(f2tf(pa[p].x), f2tf(pa[p].y), f2tf(pa[p].z), f2tf(pa[p].w));
                uint4 uw = make_uint4(f2tf(pw[p].x), f2tf(pw[p].y), f2tf(pw[p].z), f2tf(pw[p].w));
                *(uint4*)&As[lr + p * 32][lc] = ua;
                *(uint4*)&Ws[lr + p * 32][lc] = uw;
            }
        }
        __syncthreads();
    }

    // epilogue: bias + scale, float2 stores
#pragma unroll
    for (int mt = 0; mt < 4; mt++) {
        int r0 = ctaM + wm + mt * 16 + g;
        int r1 = r0 + 8;
#pragma unroll
        for (int nt = 0; nt < 4; nt++) {
            int c = ctaN + wn + nt * 8 + 2 * tg;
            float b0 = bias[c], b1 = bias[c + 1];
            float2 v0 = make_float2((acc[mt][nt][0] + b0) * scale,
                                    (acc[mt][nt][1] + b1) * scale);
            float2 v1 = make_float2((acc[mt][nt][2] + b0) * scale,
                                    (acc[mt][nt][3] + b1) * scale);
            *(float2*)&C[(size_t)r0 * N + c] = v0;
            *(float2*)&C[(size_t)r1 * N + c] = v1;
        }
    }
}

// ---------------- Flash attention (per (b,h,qtile=128)), tf32 mma ----------------
#define ALD 132   // 128 + 4 pad
#define PLD 68    // 64 + 4 pad
#define ATT_SMEM_WORDS (128*ALD + 64*ALD + 64*ALD + 128*PLD)
#define ATT_SMEM_BYTES (ATT_SMEM_WORDS * 4)

__global__ void __launch_bounds__(256, 1) attn_kernel(
    const float* __restrict__ Q, const float* __restrict__ Kp,
    const float* __restrict__ Vp, float* __restrict__ O)
{
    extern __shared__ uint32_t sm[];
    uint32_t (*Qs)[ALD] = (uint32_t(*)[ALD])sm;                          // 128 x 128
    uint32_t (*Ks)[ALD] = (uint32_t(*)[ALD])(sm + 128 * ALD);            // 64 x 128
    uint32_t (*Vs)[ALD] = (uint32_t(*)[ALD])(sm + 128 * ALD + 64 * ALD); // 64 x 128
    uint32_t (*Ps)[PLD] = (uint32_t(*)[PLD])(sm + 128 * ALD + 128 * ALD);// 128 x 64

    const int tid  = threadIdx.x;
    const int qt = blockIdx.x, h = blockIdx.y, b = blockIdx.z;
    const int warp = tid >> 5, lane = tid & 31, g = lane >> 2, tg = lane & 3;
    const int qbase = warp * 16;

    const size_t rowQ0 = (size_t)(b * SEQ + qt * 128);
    const int colH = h * HDIM;

    // load Q tile (converted to tf32)
    {
        int r = tid >> 5;           // 0..7
        int c = lane * 4;           // 0..124
#pragma unroll
        for (int p = 0; p < 16; p++) {
            int rr = r + p * 8;
            float4 v = *(const float4*)(Q + (rowQ0 + rr) * DMODEL + colH + c);
            *(uint4*)&Qs[rr][c] = make_uint4(f2tf(v.x), f2tf(v.y), f2tf(v.z), f2tf(v.w));
        }
    }

    float acc[16][4];
#pragma unroll
    for (int nt = 0; nt < 16; nt++)
#pragma unroll
        for (int j = 0; j < 4; j++) acc[nt][j] = 0.f;

    float m0 = -1e30f, m1 = -1e30f, l0 = 0.f, l1 = 0.f;

    for (int kt = 0; kt < SEQ / 64; kt++) {
        __syncthreads();   // previous iteration done reading Ks/Vs
        {
            int r = tid >> 5;
            int c = lane * 4;
            size_t rowK0 = (size_t)(b * SEQ + kt * 64);
#pragma unroll
            for (int p = 0; p < 8; p++) {
                int rr = r + p * 8;
                float4 vk = *(const float4*)(Kp + (rowK0 + rr) * DMODEL + colH + c);
                float4 vv = *(const float4*)(Vp + (rowK0 + rr) * DMODEL + colH + c);
                *(uint4*)&Ks[rr][c] = make_uint4(f2tf(vk.x), f2tf(vk.y), f2tf(vk.z), f2tf(vk.w));
                *(uint4*)&Vs[rr][c] = make_uint4(f2tf(vv.x), f2tf(vv.y), f2tf(vv.z), f2tf(vv.w));
            }
        }
        __syncthreads();

        // S = Q * K^T  (M=16 per warp, N=64, K=128) ; scale already folded into Q
        float sf[8][4];
#pragma unroll
        for (int nt = 0; nt < 8; nt++)
#pragma unroll
            for (int j = 0; j < 4; j++) sf[nt][j] = 0.f;

#pragma unroll
        for (int ks = 0; ks < 16; ks++) {
            uint32_t a[4];
            a[0] = Qs[qbase + g][ks * 8 + tg];
            a[1] = Qs[qbase + g + 8][ks * 8 + tg];
            a[2] = Qs[qbase + g][ks * 8 + tg + 4];
            a[3] = Qs[qbase + g + 8][ks * 8 + tg + 4];
#pragma unroll
            for (int nt = 0; nt < 8; nt++) {
                uint32_t bb[2];
                bb[0] = Ks[nt * 8 + g][ks * 8 + tg];
                bb[1] = Ks[nt * 8 + g][ks * 8 + tg + 4];
                mma_tf32(sf[nt], a, bb);
            }
        }

        // ---- online softmax (rows qbase+g and qbase+g+8) ----
        float tm0 = -1e30f, tm1 = -1e30f;
#pragma unroll
        for (int nt = 0; nt < 8; nt++) {
            tm0 = fmaxf(tm0, fmaxf(sf[nt][0], sf[nt][1]));
            tm1 = fmaxf(tm1, fmaxf(sf[nt][2], sf[nt][3]));
        }
        tm0 = fmaxf(tm0, __shfl_xor_sync(0xffffffffu, tm0, 1));
        tm0 = fmaxf(tm0, __shfl_xor_sync(0xffffffffu, tm0, 2));
        tm1 = fmaxf(tm1, __shfl_xor_sync(0xffffffffu, tm1, 1));
        tm1 = fmaxf(tm1, __shfl_xor_sync(0xffffffffu, tm1, 2));

        float nm0 = fmaxf(m0, tm0), nm1 = fmaxf(m1, tm1);
        float al0 = __expf(m0 - nm0), al1 = __expf(m1 - nm1);

        float ts0 = 0.f, ts1 = 0.f;
#pragma unroll
        for (int nt = 0; nt < 8; nt++) {
            sf[nt][0] = __expf(sf[nt][0] - nm0); ts0 += sf[nt][0];
            sf[nt][1] = __expf(sf[nt][1] - nm0); ts0 += sf[nt][1];
            sf[nt][2] = __expf(sf[nt][2] - nm1); ts1 += sf[nt][2];
            sf[nt][3] = __expf(sf[nt][3] - nm1); ts1 += sf[nt][3];
        }
        ts0 += __shfl_xor_sync(0xffffffffu, ts0, 1);
        ts0 += __shfl_xor_sync(0xffffffffu, ts0, 2);
        ts1 += __shfl_xor_sync(0xffffffffu, ts1, 1);
        ts1 += __shfl_xor_sync(0xffffffffu, ts1, 2);

        l0 = l0 * al0 + ts0;  l1 = l1 * al1 + ts1;
        m0 = nm0;             m1 = nm1;

#pragma unroll
        for (int nt = 0; nt < 16; nt++) {
            acc[nt][0] *= al0; acc[nt][1] *= al0;
            acc[nt][2] *= al1; acc[nt][3] *= al1;
        }

        // write P tile (warp-private rows) as tf32
#pragma unroll
        for (int nt = 0; nt < 8; nt++) {
            Ps[qbase + g][nt * 8 + 2 * tg]         = f2tf(sf[nt][0]);
            Ps[qbase + g][nt * 8 + 2 * tg + 1]     = f2tf(sf[nt][1]);
            Ps[qbase + g + 8][nt * 8 + 2 * tg]     = f2tf(sf[nt][2]);
            Ps[qbase + g + 8][nt * 8 + 2 * tg + 1] = f2tf(sf[nt][3]);
        }
        __syncwarp();

        // acc += P @ V  (M=16, N=128, K=64)
#pragma unroll
        for (int ks = 0; ks < 8; ks++) {
            uint32_t a[4];
            a[0] = Ps[qbase + g][ks * 8 + tg];
            a[1] = Ps[qbase + g + 8][ks * 8 + tg];
            a[2] = Ps[qbase + g][ks * 8 + tg + 4];
            a[3] = Ps[qbase + g + 8][ks * 8 + tg + 4];
#pragma unroll
            for (int nt = 0; nt < 16; nt++) {
                uint32_t bb[2];
                bb[0] = Vs[ks * 8 + tg][nt * 8 + g];
                bb[1] = Vs[ks * 8 + tg + 4][nt * 8 + g];
                mma_tf32(acc[nt], a, bb);
            }
        }
        __syncwarp();
    }

    // epilogue: normalize, write to [B*S, D] at head column
    float inv0 = 1.f / l0, inv1 = 1.f / l1;
    size_t r0 = rowQ0 + qbase + g;
    size_t r1 = r0 + 8;
#pragma unroll
    for (int nt = 0; nt < 16; nt++) {
        int c = colH + nt * 8 + 2 * tg;
        *(float2*)&O[r0 * DMODEL + c] = make_float2(acc[nt][0] * inv0, acc[nt][1] * inv0);
        *(float2*)&O[r1 * DMODEL + c] = make_float2(acc[nt][2] * inv1, acc[nt][3] * inv1);
    }
}

// ---------------- launch ----------------
extern "C" void kernel_launch(void* const* d_in, const int* in_sizes, int n_in,
                              void* d_out, int out_size)
{
    const float* query  = (const float*)d_in[0];
    const float* key_in = (const float*)d_in[1];
    const float* value  = (const float*)d_in[2];
    const float* Wq = (const float*)d_in[3];
    const float* bq = (const float*)d_in[4];
    const float* Wk = (const float*)d_in[5];
    const float* bk = (const float*)d_in[6];
    const float* Wv = (const float*)d_in[7];
    const float* bv = (const float*)d_in[8];
    const float* Wo = (const float*)d_in[9];
    const float* bo = (const float*)d_in[10];
    float* out = (float*)d_out;

    float *gq, *gk, *gv, *ga;
    cudaGetSymbolAddress((void**)&gq, g_q);
    cudaGetSymbolAddress((void**)&gk, g_k);
    cudaGetSymbolAddress((void**)&gv, g_v);
    cudaGetSymbolAddress((void**)&ga, g_att);

    cudaFuncSetAttribute(attn_kernel,
                         cudaFuncAttributeMaxDynamicSharedMemorySize, ATT_SMEM_BYTES);

    dim3 ggrid(DMODEL / 128, MROWS / 128);   // (16, 32)
    const float qscale = 0.08838834764831845f;   // 1/sqrt(128)

    gemm_bias_tf32<<<ggrid, 256>>>(query,  Wq, bq, gq, MROWS, DMODEL, DMODEL, qscale);
    gemm_bias_tf32<<<ggrid, 256>>>(key_in, Wk, bk, gk, MROWS, DMODEL, DMODEL, 1.0f);
    gemm_bias_tf32<<<ggrid, 256>>>(value,  Wv, bv, gv, MROWS, DMODEL, DMODEL, 1.0f);

    attn_kernel<<<dim3(SEQ / 128, NHEADS, BATCH), 256, ATT_SMEM_BYTES>>>(gq, gk, gv, ga);

    gemm_bias_tf32<<<ggrid, 256>>>(ga, Wo, bo, out, MROWS, DMODEL, DMODEL, 1.0f);
}

// round 8
// speedup vs baseline: 1.0688x; 1.0688x over previous
#include <cuda_runtime.h>
#include <cstdint>
#include <cstdio>

#define DMODEL 2048
#define NHEADS 16
#define HDIM   128
#define BATCH  2
#define SEQ    2048
#define MROWS  (BATCH*SEQ)   // 4096

// ---------------- scratch (device globals: allocation-free) ----------------
__device__ float g_q[(size_t)MROWS * DMODEL];
__device__ float g_k[(size_t)MROWS * DMODEL];
__device__ float g_v[(size_t)MROWS * DMODEL];
__device__ float g_att[(size_t)MROWS * DMODEL];

// ---------------- helpers ----------------
__device__ __forceinline__ uint32_t f2tf(float x) {
    uint32_t r;
    asm("cvt.rna.tf32.f32 %0, %1;" : "=r"(r) : "f"(x));
    return r;
}

__device__ __forceinline__ void mma_tf32(float* c, const uint32_t* a, const uint32_t* b) {
    asm("mma.sync.aligned.m16n8k8.row.col.f32.tf32.tf32.f32 "
        "{%0,%1,%2,%3}, {%4,%5,%6,%7}, {%8,%9}, {%0,%1,%2,%3};"
        : "+f"(c[0]), "+f"(c[1]), "+f"(c[2]), "+f"(c[3])
        : "r"(a[0]), "r"(a[1]), "r"(a[2]), "r"(a[3]),
          "r"(b[0]), "r"(b[1]));
}

// ---------------- GEMM body: C = (A @ W^T + bias) * scale ----------------
// CTA tile 128x128, k-tile 32, 8 warps (2x4), warp tile 64x32, m16n8k8 tf32.
// M=MROWS, N=K=DMODEL compile-time.
#define GT_K 32
#define GLD  36   // 32 + 4 pad (stride%32==4 -> conflict-free frag loads)

__device__ __forceinline__ void gemm_body(
    const float* __restrict__ A, const float* __restrict__ W,
    const float* __restrict__ bias, float* __restrict__ C, float scale)
{
    __shared__ uint32_t As[128][GLD];
    __shared__ uint32_t Ws[128][GLD];

    const int tid  = threadIdx.x;
    const int ctaN = blockIdx.x * 128;
    const int ctaM = blockIdx.y * 128;

    const int warp = tid >> 5, lane = tid & 31;
    const int g = lane >> 2, tg = lane & 3;
    const int wm = (warp & 1) * 64;
    const int wn = (warp >> 1) * 32;

    const int lr = tid >> 3;        // 0..31
    const int lc = (tid & 7) * 4;   // 0..28

    const float* Abase = A + (size_t)(ctaM + lr) * DMODEL + lc;
    const float* Wbase = W + (size_t)(ctaN + lr) * DMODEL + lc;

    float acc[4][4][4];
#pragma unroll
    for (int mt = 0; mt < 4; mt++)
#pragma unroll
        for (int nt = 0; nt < 4; nt++)
#pragma unroll
            for (int j = 0; j < 4; j++) acc[mt][nt][j] = 0.f;

    const int nk = DMODEL / GT_K;

    // preload tile 0 into smem (converted to tf32)
#pragma unroll
    for (int p = 0; p < 4; p++) {
        float4 va = *(const float4*)(Abase + (size_t)(p * 32) * DMODEL);
        float4 vw = *(const float4*)(Wbase + (size_t)(p * 32) * DMODEL);
        *(uint4*)&As[lr + p * 32][lc] = make_uint4(f2tf(va.x), f2tf(va.y), f2tf(va.z), f2tf(va.w));
        *(uint4*)&Ws[lr + p * 32][lc] = make_uint4(f2tf(vw.x), f2tf(vw.y), f2tf(vw.z), f2tf(vw.w));
    }
    __syncthreads();

    for (int kt = 0; kt < nk; kt++) {
        float4 pa[4], pw[4];
        const bool pre = (kt + 1 < nk);
        if (pre) {
            const float* An = Abase + (size_t)(kt + 1) * GT_K;
            const float* Wn = Wbase + (size_t)(kt + 1) * GT_K;
#pragma unroll
            for (int p = 0; p < 4; p++) {
                pa[p] = *(const float4*)(An + (size_t)(p * 32) * DMODEL);
                pw[p] = *(const float4*)(Wn + (size_t)(p * 32) * DMODEL);
            }
        }

#pragma unroll
        for (int ks = 0; ks < 4; ks++) {
            uint32_t a[4][4];
#pragma unroll
            for (int mt = 0; mt < 4; mt++) {
                int r = wm + mt * 16 + g;
                int c = ks * 8 + tg;
                a[mt][0] = As[r][c];
                a[mt][1] = As[r + 8][c];
                a[mt][2] = As[r][c + 4];
                a[mt][3] = As[r + 8][c + 4];
            }
            uint32_t bfr[4][2];
#pragma unroll
            for (int nt = 0; nt < 4; nt++) {
                int rn = wn + nt * 8 + g;
                bfr[nt][0] = Ws[rn][ks * 8 + tg];
                bfr[nt][1] = Ws[rn][ks * 8 + tg + 4];
            }
#pragma unroll
            for (int mt = 0; mt < 4; mt++)
#pragma unroll
                for (int nt = 0; nt < 4; nt++)
                    mma_tf32(acc[mt][nt], a[mt], bfr[nt]);
        }
        __syncthreads();
        if (pre) {
#pragma unroll
            for (int p = 0; p < 4; p++) {
                *(uint4*)&As[lr + p * 32][lc] = make_uint4(f2tf(pa[p].x), f2tf(pa[p].y), f2tf(pa[p].z), f2tf(pa[p].w));
                *(uint4*)&Ws[lr + p * 32][lc] = make_uint4(f2tf(pw[p].x), f2tf(pw[p].y), f2tf(pw[p].z), f2tf(pw[p].w));
            }
        }
        __syncthreads();
    }

    // epilogue: bias + scale, float2 stores
#pragma unroll
    for (int mt = 0; mt < 4; mt++) {
        int r0 = ctaM + wm + mt * 16 + g;
        int r1 = r0 + 8;
#pragma unroll
        for (int nt = 0; nt < 4; nt++) {
            int c = ctaN + wn + nt * 8 + 2 * tg;
            float b0 = bias[c], b1 = bias[c + 1];
            *(float2*)&C[(size_t)r0 * DMODEL + c] =
                make_float2((acc[mt][nt][0] + b0) * scale, (acc[mt][nt][1] + b1) * scale);
            *(float2*)&C[(size_t)r1 * DMODEL + c] =
                make_float2((acc[mt][nt][2] + b0) * scale, (acc[mt][nt][3] + b1) * scale);
        }
    }
}

// Fused Q/K/V projections: blockIdx.z selects which projection.
__global__ void __launch_bounds__(256, 1) gemm_qkv(
    const float* __restrict__ q_in, const float* __restrict__ k_in, const float* __restrict__ v_in,
    const float* __restrict__ Wq, const float* __restrict__ bq,
    const float* __restrict__ Wk, const float* __restrict__ bk,
    const float* __restrict__ Wv, const float* __restrict__ bv,
    float* __restrict__ Cq, float* __restrict__ Ck, float* __restrict__ Cv,
    float qscale)
{
    const int z = blockIdx.z;
    const float* A   = (z == 0) ? q_in : (z == 1) ? k_in : v_in;
    const float* W   = (z == 0) ? Wq   : (z == 1) ? Wk   : Wv;
    const float* bia = (z == 0) ? bq   : (z == 1) ? bk   : bv;
    float*       C   = (z == 0) ? Cq   : (z == 1) ? Ck   : Cv;
    float        s   = (z == 0) ? qscale : 1.0f;
    gemm_body(A, W, bia, C, s);
}

__global__ void __launch_bounds__(256, 1) gemm_o(
    const float* __restrict__ A, const float* __restrict__ W,
    const float* __restrict__ bias, float* __restrict__ C)
{
    gemm_body(A, W, bias, C, 1.0f);
}

// ---------------- Flash attention (per (b,h,qtile=128)), tf32 mma ----------------
// Software-pipelined: next K tile prefetched to registers during S-MMA,
// next V tile prefetched before softmax; both stored to smem after PV-MMA.
#define ALD 132   // 128 + 4 pad
#define PLD 68    // 64 + 4 pad
#define ATT_SMEM_WORDS (128*ALD + 64*ALD + 64*ALD + 128*PLD)
#define ATT_SMEM_BYTES (ATT_SMEM_WORDS * 4)

__global__ void __launch_bounds__(256, 1) attn_kernel(
    const float* __restrict__ Q, const float* __restrict__ Kp,
    const float* __restrict__ Vp, float* __restrict__ O)
{
    extern __shared__ uint32_t sm[];
    uint32_t (*Qs)[ALD] = (uint32_t(*)[ALD])sm;                          // 128 x 128
    uint32_t (*Ks)[ALD] = (uint32_t(*)[ALD])(sm + 128 * ALD);            // 64 x 128
    uint32_t (*Vs)[ALD] = (uint32_t(*)[ALD])(sm + 128 * ALD + 64 * ALD); // 64 x 128
    uint32_t (*Ps)[PLD] = (uint32_t(*)[PLD])(sm + 128 * ALD + 128 * ALD);// 128 x 64

    const int tid  = threadIdx.x;
    const int qt = blockIdx.x, h = blockIdx.y, b = blockIdx.z;
    const int warp = tid >> 5, lane = tid & 31, g = lane >> 2, tg = lane & 3;
    const int qbase = warp * 16;

    const size_t rowQ0 = (size_t)(b * SEQ + qt * 128);
    const int colH = h * HDIM;

    const int ldr = tid >> 5;       // 0..7  (loader row)
    const int ldc = lane * 4;       // 0..124

    // load Q tile (converted to tf32)
#pragma unroll
    for (int p = 0; p < 16; p++) {
        int rr = ldr + p * 8;
        float4 v = *(const float4*)(Q + (rowQ0 + rr) * DMODEL + colH + ldc);
        *(uint4*)&Qs[rr][ldc] = make_uint4(f2tf(v.x), f2tf(v.y), f2tf(v.z), f2tf(v.w));
    }

    // load K/V tile 0
    {
        size_t rowK0 = (size_t)(b * SEQ);
#pragma unroll
        for (int p = 0; p < 8; p++) {
            int rr = ldr + p * 8;
            float4 vk = *(const float4*)(Kp + (rowK0 + rr) * DMODEL + colH + ldc);
            float4 vv = *(const float4*)(Vp + (rowK0 + rr) * DMODEL + colH + ldc);
            *(uint4*)&Ks[rr][ldc] = make_uint4(f2tf(vk.x), f2tf(vk.y), f2tf(vk.z), f2tf(vk.w));
            *(uint4*)&Vs[rr][ldc] = make_uint4(f2tf(vv.x), f2tf(vv.y), f2tf(vv.z), f2tf(vv.w));
        }
    }
    __syncthreads();

    float acc[16][4];
#pragma unroll
    for (int nt = 0; nt < 16; nt++)
#pragma unroll
        for (int j = 0; j < 4; j++) acc[nt][j] = 0.f;

    float m0 = -1e30f, m1 = -1e30f, l0 = 0.f, l1 = 0.f;

    for (int kt = 0; kt < SEQ / 64; kt++) {
        const bool pre = (kt + 1 < SEQ / 64);
        const size_t rowKn = (size_t)(b * SEQ + (kt + 1) * 64);

        // issue next-K prefetch (consumed only after the bar below -> overlaps S-MMA)
        float4 kf[8];
        if (pre) {
#pragma unroll
            for (int p = 0; p < 8; p++)
                kf[p] = *(const float4*)(Kp + (rowKn + ldr + p * 8) * DMODEL + colH + ldc);
        }

        // S = Q * K^T  (M=16 per warp, N=64, K=128); 1/sqrt(dh) folded into Q
        float sf[8][4];
#pragma unroll
        for (int nt = 0; nt < 8; nt++)
#pragma unroll
            for (int j = 0; j < 4; j++) sf[nt][j] = 0.f;

#pragma unroll
        for (int ks = 0; ks < 16; ks++) {
            uint32_t a[4];
            a[0] = Qs[qbase + g][ks * 8 + tg];
            a[1] = Qs[qbase + g + 8][ks * 8 + tg];
            a[2] = Qs[qbase + g][ks * 8 + tg + 4];
            a[3] = Qs[qbase + g + 8][ks * 8 + tg + 4];
#pragma unroll
            for (int nt = 0; nt < 8; nt++) {
                uint32_t bb[2];
                bb[0] = Ks[nt * 8 + g][ks * 8 + tg];
                bb[1] = Ks[nt * 8 + g][ks * 8 + tg + 4];
                mma_tf32(sf[nt], a, bb);
            }
        }

        // issue next-V prefetch (overlaps softmax + PV-MMA)
        float4 vf[8];
        if (pre) {
#pragma unroll
            for (int p = 0; p < 8; p++)
                vf[p] = *(const float4*)(Vp + (rowKn + ldr + p * 8) * DMODEL + colH + ldc);
        }

        // ---- online softmax (rows qbase+g and qbase+g+8) ----
        float tm0 = -1e30f, tm1 = -1e30f;
#pragma unroll
        for (int nt = 0; nt < 8; nt++) {
            tm0 = fmaxf(tm0, fmaxf(sf[nt][0], sf[nt][1]));
            tm1 = fmaxf(tm1, fmaxf(sf[nt][2], sf[nt][3]));
        }
        tm0 = fmaxf(tm0, __shfl_xor_sync(0xffffffffu, tm0, 1));
        tm0 = fmaxf(tm0, __shfl_xor_sync(0xffffffffu, tm0, 2));
        tm1 = fmaxf(tm1, __shfl_xor_sync(0xffffffffu, tm1, 1));
        tm1 = fmaxf(tm1, __shfl_xor_sync(0xffffffffu, tm1, 2));

        float nm0 = fmaxf(m0, tm0), nm1 = fmaxf(m1, tm1);
        float al0 = __expf(m0 - nm0), al1 = __expf(m1 - nm1);

        float ts0 = 0.f, ts1 = 0.f;
#pragma unroll
        for (int nt = 0; nt < 8; nt++) {
            sf[nt][0] = __expf(sf[nt][0] - nm0); ts0 += sf[nt][0];
            sf[nt][1] = __expf(sf[nt][1] - nm0); ts0 += sf[nt][1];
            sf[nt][2] = __expf(sf[nt][2] - nm1); ts1 += sf[nt][2];
            sf[nt][3] = __expf(sf[nt][3] - nm1); ts1 += sf[nt][3];
        }
        ts0 += __shfl_xor_sync(0xffffffffu, ts0, 1);
        ts0 += __shfl_xor_sync(0xffffffffu, ts0, 2);
        ts1 += __shfl_xor_sync(0xffffffffu, ts1, 1);
        ts1 += __shfl_xor_sync(0xffffffffu, ts1, 2);

        l0 = l0 * al0 + ts0;  l1 = l1 * al1 + ts1;
        m0 = nm0;             m1 = nm1;

#pragma unroll
        for (int nt = 0; nt < 16; nt++) {
            acc[nt][0] *= al0; acc[nt][1] *= al0;
            acc[nt][2] *= al1; acc[nt][3] *= al1;
        }

        // write P tile (warp-private rows) as tf32
#pragma unroll
        for (int nt = 0; nt < 8; nt++) {
            Ps[qbase + g][nt * 8 + 2 * tg]         = f2tf(sf[nt][0]);
            Ps[qbase + g][nt * 8 + 2 * tg + 1]     = f2tf(sf[nt][1]);
            Ps[qbase + g + 8][nt * 8 + 2 * tg]     = f2tf(sf[nt][2]);
            Ps[qbase + g + 8][nt * 8 + 2 * tg + 1] = f2tf(sf[nt][3]);
        }
        __syncwarp();

        // acc += P @ V  (M=16, N=128, K=64)
#pragma unroll
        for (int ks = 0; ks < 8; ks++) {
            uint32_t a[4];
            a[0] = Ps[qbase + g][ks * 8 + tg];
            a[1] = Ps[qbase + g + 8][ks * 8 + tg];
            a[2] = Ps[qbase + g][ks * 8 + tg + 4];
            a[3] = Ps[qbase + g + 8][ks * 8 + tg + 4];
#pragma unroll
            for (int nt = 0; nt < 16; nt++) {
                uint32_t bb[2];
                bb[0] = Vs[ks * 8 + tg][nt * 8 + g];
                bb[1] = Vs[ks * 8 + tg + 4][nt * 8 + g];
                mma_tf32(acc[nt], a, bb);
            }
        }

        // swap in the prefetched tiles
        __syncthreads();   // all warps done reading Ks/Vs
        if (pre) {
#pragma unroll
            for (int p = 0; p < 8; p++) {
                int rr = ldr + p * 8;
                *(uint4*)&Ks[rr][ldc] = make_uint4(f2tf(kf[p].x), f2tf(kf[p].y), f2tf(kf[p].z), f2tf(kf[p].w));
                *(uint4*)&Vs[rr][ldc] = make_uint4(f2tf(vf[p].x), f2tf(vf[p].y), f2tf(vf[p].z), f2tf(vf[p].w));
            }
            __syncthreads();   // new tiles visible
        }
    }

    // epilogue: normalize, write to [B*S, D] at head column
    float inv0 = 1.f / l0, inv1 = 1.f / l1;
    size_t r0 = rowQ0 + qbase + g;
    size_t r1 = r0 + 8;
#pragma unroll
    for (int nt = 0; nt < 16; nt++) {
        int c = colH + nt * 8 + 2 * tg;
        *(float2*)&O[r0 * DMODEL + c] = make_float2(acc[nt][0] * inv0, acc[nt][1] * inv0);
        *(float2*)&O[r1 * DMODEL + c] = make_float2(acc[nt][2] * inv1, acc[nt][3] * inv1);
    }
}

// ---------------- launch ----------------
extern "C" void kernel_launch(void* const* d_in, const int* in_sizes, int n_in,
                              void* d_out, int out_size)
{
    const float* query  = (const float*)d_in[0];
    const float* key_in = (const float*)d_in[1];
    const float* value  = (const float*)d_in[2];
    const float* Wq = (const float*)d_in[3];
    const float* bq = (const float*)d_in[4];
    const float* Wk = (const float*)d_in[5];
    const float* bk = (const float*)d_in[6];
    const float* Wv = (const float*)d_in[7];
    const float* bv = (const float*)d_in[8];
    const float* Wo = (const float*)d_in[9];
    const float* bo = (const float*)d_in[10];
    float* out = (float*)d_out;

    float *gq, *gk, *gv, *ga;
    cudaGetSymbolAddress((void**)&gq, g_q);
    cudaGetSymbolAddress((void**)&gk, g_k);
    cudaGetSymbolAddress((void**)&gv, g_v);
    cudaGetSymbolAddress((void**)&ga, g_att);

    cudaFuncSetAttribute(attn_kernel,
                         cudaFuncAttributeMaxDynamicSharedMemorySize, ATT_SMEM_BYTES);

    const float qscale = 0.08838834764831845f;   // 1/sqrt(128)

    dim3 qkv_grid(DMODEL / 128, MROWS / 128, 3);   // (16, 32, 3) = 1536 CTAs
    gemm_qkv<<<qkv_grid, 256>>>(query, key_in, value,
                                Wq, bq, Wk, bk, Wv, bv,
                                gq, gk, gv, qscale);

    attn_kernel<<<dim3(SEQ / 128, NHEADS, BATCH), 256, ATT_SMEM_BYTES>>>(gq, gk, gv, ga);

    gemm_o<<<dim3(DMODEL / 128, MROWS / 128), 256>>>(ga, Wo, bo, out);
}